// round 15
// baseline (speedup 1.0000x reference)
#include <cuda_runtime.h>
#include <cuda_fp16.h>
#include <cstdint>
#include <math.h>

// ---------------- problem constants ----------------
#define BB   4
#define NN   256
#define DD   384
#define LL   12
#define F1C  1536
#define F2C  384
#define MM   8
#define HH   4
#define TT   260          // 4 skill tokens + 256
#define DH   96           // D / H
#define ROWS (BB*TT)      // 1040
#define TTP  272          // TT padded to multiple of 16

#define GCNT   (LL*F1C*F2C)          // 7,077,888 groups per side
#define OUTROW (2LL*GCNT)

// ---------------- fp32 scratch ----------------
#define OFF_TOK  0
#define SZ_TOK   (ROWS*DD)
#define OFF_SC   (OFF_TOK + SZ_TOK)
#define SZ_SC    (BB*HH*TT*TT)
#define OFF_O    (OFF_SC + SZ_SC)
#define SZ_O     (ROWS*DD)
#define OFF_W    (OFF_O + SZ_O)
#define SZ_W     32
#define SCRATCH_TOTAL (OFF_W + SZ_W)
__device__ float g_scratch[SCRATCH_TOTAL];

// ---------------- fp16 scratch (offsets in halves) ----------------
#define HX_OFF     0
#define HWP_OFF    393216
#define HWQKV_OFF  540672
#define HWO_OFF    983040
#define HW1_OFF    1130496
#define HW2_OFF    1425408
#define HQ_OFF     1720320
#define HKT_OFF    2119680
#define HV_OFF     2537472
#define HPR_OFF    2955264
#define HY_OFF     4086784
#define HOB_OFF    4486144
#define HFF_OFF    4885504
#define HTOTAL     5684224
__device__ __half g_half[HTOTAL];

__device__ __forceinline__ float tanh_fast(float x)
{
    float r;
    asm("tanh.approx.f32 %0, %1;" : "=f"(r) : "f"(x));
    return r;
}

__device__ __forceinline__ void cp16(void* smem, const void* gmem, bool pred)
{
    unsigned int saddr = (unsigned int)__cvta_generic_to_shared(smem);
    int sz = pred ? 16 : 0;
    asm volatile("cp.async.cg.shared.global [%0], [%1], 16, %2;"
                 :: "r"(saddr), "l"(gmem), "r"(sz) : "memory");
}

// ---------------- fp32 -> fp16 conversion of x + weights, + skill-token fill ----------------
#define CONV_N 1720320
__global__ void conv_kernel(const float* __restrict__ x,  const float* __restrict__ Wp,
                            const float* __restrict__ Wqkv, const float* __restrict__ Wo,
                            const float* __restrict__ W1, const float* __restrict__ W2,
                            const float* __restrict__ skills, float* __restrict__ tok)
{
    int i = blockIdx.x * 256 + threadIdx.x;
    if (i >= CONV_N) {
        int i2 = i - CONV_N;
        if (i2 < BB * 4 * DD) {
            int b = i2 / (4 * DD);
            int r = i2 % (4 * DD);
            tok[(size_t)(b * TT) * DD + r] = skills[r];
        }
        return;
    }
    float v;
    if      (i < 393216)  v = x[i];
    else if (i < 540672)  v = Wp[i - 393216];
    else if (i < 983040)  v = Wqkv[i - 540672];
    else if (i < 1130496) v = Wo[i - 983040];
    else if (i < 1425408) v = W1[i - 1130496];
    else                  v = W2[i - 1425408];
    g_half[i] = __float2half_rn(v);
}

// ---------------- epilogue helper ----------------
// epi: 0=none, 1=gelu->half only, 2=+R[col], 3=+Rm residual, 4=qkv scatter
__device__ __forceinline__ void epi_store2(
    float v0, float v1, int row, int col, int Mr, int N,
    const float* bias, const float* R, const float* Rm,
    float* C, __half* hC, int ldc, float scale, int epi)
{
    if (row >= Mr || col >= N) return;
    float b0 = 0.f, b1 = 0.f;
    if (bias) { b0 = bias[col]; b1 = bias[col + 1]; }
    v0 = v0 * scale + b0;
    v1 = v1 * scale + b1;
    if (epi == 1) {
        float t;
        t = v0; v0 = 0.5f * t * (1.f + tanh_fast(0.7978845608028654f * (t + 0.044715f * t * t * t)));
        t = v1; v1 = 0.5f * t * (1.f + tanh_fast(0.7978845608028654f * (t + 0.044715f * t * t * t)));
    } else if (epi == 2) {
        v0 += R[col]; v1 += R[col + 1];
    } else if (epi == 3) {
        const float* rr = Rm + (size_t)row * ldc + col;
        v0 += rr[0]; v1 += rr[1];
    }
    if (epi == 4) {
        int b = row / TT, t = row - b * TT;
        int s = col / DD;
        int rem = col - s * DD;
        int h = rem / DH;
        int d = rem - h * DH;
        int bh = b * HH + h;
        if (s == 0) {
            *(__half2*)(g_half + HQ_OFF + ((size_t)(bh * TT + t)) * DH + d) =
                __floats2half2_rn(v0, v1);
        } else if (s == 1) {
            g_half[HKT_OFF + ((size_t)(bh * DH + d)) * TTP + t]     = __float2half_rn(v0);
            g_half[HKT_OFF + ((size_t)(bh * DH + d + 1)) * TTP + t] = __float2half_rn(v1);
        } else {
            *(__half2*)(g_half + HV_OFF + ((size_t)(bh * TTP + t)) * DH + d) =
                __floats2half2_rn(v0, v1);
        }
        return;
    }
    if (C)  *(float2*)(C + (size_t)row * ldc + col) = make_float2(v0, v1);
    if (hC) *(__half2*)(hC + (size_t)row * ldc + col) = __floats2half2_rn(v0, v1);
}

// ---------------- fp16 tensor-core GEMM: CTA 64xBN, K-slab 32, 3-stage cp.async ----------------
// 8 warps in 4x2 grid; warp tile 16 x (BN/2)
template<int BN>
__global__ void __launch_bounds__(256) hgemm_kernel(
    const __half* __restrict__ A, const __half* __restrict__ B,
    const float* __restrict__ bias, const float* __restrict__ R,
    float* __restrict__ C, __half* __restrict__ hC,
    int Mr, int N, int K, int lda, int ldb, int Nload,
    long long aBS, long long wBS, long long cBS1, long long cBS2, int cdiv,
    int ldc, float scale, int epi)
{
    const int NLD = BN / 64;          // B uint4 loads per thread
    const int PLD = BN / 32;          // ldmatrix.trans per kk per warp
    const int NTC = BN / 16;          // 8-col accumulator chunks per warp

    int z = blockIdx.z;
    A += (size_t)z * aBS;
    B += (size_t)z * wBS;
    size_t coff = (size_t)(z / cdiv) * cBS1 + (size_t)(z % cdiv) * cBS2;
    if (C)  C += coff;
    if (hC) hC += coff;
    const float* Rm = (epi == 3) ? (R + coff) : nullptr;

    __shared__ __half As[3][64][40];
    __shared__ __half Bs[3][32][BN + 8];

    int bm = blockIdx.y * 64, bn = blockIdx.x * BN;
    int tid = threadIdx.x;
    int lane = tid & 31, warp = tid >> 5;
    int wm = warp >> 1, wn = warp & 1;

    int ar = tid >> 2;
    int ac = (tid & 3) << 3;
    int arow = bm + ar;
    bool a_row_ok = arow < Mr;
    const __half* Ap = A + (size_t)(a_row_ok ? arow : 0) * lda + ac;

    int brj[NLD], bcj[NLD];
    bool okj[NLD];
    const __half* Bpj[NLD];
#pragma unroll
    for (int j = 0; j < NLD; j++) {
        int idx = j * 256 + tid;
        brj[j] = idx / (BN / 8);
        bcj[j] = (idx % (BN / 8)) * 8;
        okj[j] = (bn + bcj[j]) < Nload;
        Bpj[j] = B + (size_t)brj[j] * ldb + (okj[j] ? bn + bcj[j] : 0);
    }

    float acc[NTC][4];
#pragma unroll
    for (int nt = 0; nt < NTC; nt++)
#pragma unroll
        for (int i = 0; i < 4; i++) acc[nt][i] = 0.f;

    // prologue: issue slabs 0 and 1
#pragma unroll
    for (int s = 0; s < 2; s++) {
        int k0 = s * 32;
        bool pa = a_row_ok && (k0 + ac) < K;
        cp16(&As[s][ar][ac], pa ? (Ap + k0) : Ap, pa);
#pragma unroll
        for (int j = 0; j < NLD; j++) {
            bool pb = okj[j] && (k0 + brj[j]) < K;
            cp16(&Bs[s][brj[j]][bcj[j]], pb ? (Bpj[j] + (size_t)k0 * ldb) : Bpj[j], pb);
        }
        asm volatile("cp.async.commit_group;" ::: "memory");
    }

    int lb = lane >> 3, lr = lane & 7;
    int frag_row = (lb & 1) * 8 + lr;
    int frag_col = (lb >> 1) * 8;

    int cur = 0;
    for (int k0 = 0; k0 < K; k0 += 32) {
        asm volatile("cp.async.wait_group 1;" ::: "memory");
        __syncthreads();

        {
            int kn = k0 + 64;
            int nst = cur + 2; if (nst >= 3) nst -= 3;
            bool pa = a_row_ok && (kn + ac) < K;
            cp16(&As[nst][ar][ac], pa ? (Ap + kn) : Ap, pa);
#pragma unroll
            for (int j = 0; j < NLD; j++) {
                bool pb = okj[j] && (kn + brj[j]) < K;
                cp16(&Bs[nst][brj[j]][bcj[j]], pb ? (Bpj[j] + (size_t)kn * ldb) : Bpj[j], pb);
            }
            asm volatile("cp.async.commit_group;" ::: "memory");
        }

        unsigned int afr[2][4];
        unsigned int bfr[2][NTC][2];
#pragma unroll
        for (int kk = 0; kk < 2; kk++) {
            unsigned int addr = (unsigned int)__cvta_generic_to_shared(
                &As[cur][wm * 16 + frag_row][kk * 16 + frag_col]);
            asm volatile("ldmatrix.sync.aligned.m8n8.x4.shared.b16 {%0,%1,%2,%3}, [%4];"
                : "=r"(afr[kk][0]), "=r"(afr[kk][1]), "=r"(afr[kk][2]), "=r"(afr[kk][3])
                : "r"(addr));
        }
#pragma unroll
        for (int kk = 0; kk < 2; kk++)
#pragma unroll
            for (int p = 0; p < PLD; p++) {
                unsigned int addr = (unsigned int)__cvta_generic_to_shared(
                    &Bs[cur][kk * 16 + frag_row][wn * (BN / 2) + p * 16 + frag_col]);
                asm volatile("ldmatrix.sync.aligned.m8n8.x4.trans.shared.b16 {%0,%1,%2,%3}, [%4];"
                    : "=r"(bfr[kk][p * 2][0]), "=r"(bfr[kk][p * 2][1]),
                      "=r"(bfr[kk][p * 2 + 1][0]), "=r"(bfr[kk][p * 2 + 1][1])
                    : "r"(addr));
            }
#pragma unroll
        for (int kk = 0; kk < 2; kk++)
#pragma unroll
            for (int nt = 0; nt < NTC; nt++) {
                asm volatile(
                    "mma.sync.aligned.m16n8k16.row.col.f32.f16.f16.f32 "
                    "{%0,%1,%2,%3}, {%4,%5,%6,%7}, {%8,%9}, {%0,%1,%2,%3};"
                    : "+f"(acc[nt][0]), "+f"(acc[nt][1]),
                      "+f"(acc[nt][2]), "+f"(acc[nt][3])
                    : "r"(afr[kk][0]), "r"(afr[kk][1]), "r"(afr[kk][2]), "r"(afr[kk][3]),
                      "r"(bfr[kk][nt][0]), "r"(bfr[kk][nt][1]));
            }

        cur = cur + 1; if (cur >= 3) cur -= 3;
    }

    int g = lane >> 2, t2 = (lane & 3) << 1;
    int row0 = bm + wm * 16 + g;
#pragma unroll
    for (int nt = 0; nt < NTC; nt++) {
        int col = bn + wn * (BN / 2) + nt * 8 + t2;
        epi_store2(acc[nt][0], acc[nt][1], row0,     col, Mr, N,
                   bias, R, Rm, C, hC, ldc, scale, epi);
        epi_store2(acc[nt][2], acc[nt][3], row0 + 8, col, Mr, N,
                   bias, R, Rm, C, hC, ldc, scale, epi);
    }
}

// ---------------- layernorm: 1 warp/row, 8 rows/block, barrier-free ----------------
__global__ void __launch_bounds__(256) ln_kernel(
    const float* __restrict__ X, const float* __restrict__ gw,
    const float* __restrict__ bw, __half* __restrict__ Y)
{
    int warp = threadIdx.x >> 5;
    int lane = threadIdx.x & 31;
    int row = blockIdx.x * 8 + warp;
    const float* x = X + (size_t)row * DD;

    float4 v[3];
    float s = 0.f, q = 0.f;
#pragma unroll
    for (int k = 0; k < 3; k++) {
        v[k] = *(const float4*)(x + lane * 4 + k * 128);
        s += v[k].x + v[k].y + v[k].z + v[k].w;
        q += v[k].x * v[k].x + v[k].y * v[k].y + v[k].z * v[k].z + v[k].w * v[k].w;
    }
#pragma unroll
    for (int o = 16; o; o >>= 1) {
        s += __shfl_xor_sync(0xffffffffu, s, o);
        q += __shfl_xor_sync(0xffffffffu, q, o);
    }
    float mean = s * (1.f / DD);
    float var = q * (1.f / DD) - mean * mean;
    float inv = rsqrtf(var + 1e-6f);

    __half* y = Y + (size_t)row * DD;
#pragma unroll
    for (int k = 0; k < 3; k++) {
        int d = lane * 4 + k * 128;
        float4 g4 = *(const float4*)(gw + d);
        float4 b4 = *(const float4*)(bw + d);
        float r0 = (v[k].x - mean) * inv * g4.x + b4.x;
        float r1 = (v[k].y - mean) * inv * g4.y + b4.y;
        float r2 = (v[k].z - mean) * inv * g4.z + b4.z;
        float r3 = (v[k].w - mean) * inv * g4.w + b4.w;
        __half2 h0 = __floats2half2_rn(r0, r1);
        __half2 h1 = __floats2half2_rn(r2, r3);
        uint2 pk;
        pk.x = *(unsigned int*)&h0;
        pk.y = *(unsigned int*)&h1;
        *(uint2*)(y + d) = pk;
    }
}

// ---------------- softmax over 260 cols: fp32 scores -> half probs (stride 272) ----------------
__global__ void __launch_bounds__(128) softmax260_kernel(
    const float* __restrict__ S, __half* __restrict__ P)
{
    int row = blockIdx.x;
    const float* p = S + (size_t)row * TT;
    __half* ph = P + (size_t)row * TTP;
    int tid = threadIdx.x;
    float v0 = p[tid], v1 = p[tid + 128];
    float v2 = (tid < 4) ? p[tid + 256] : -1e30f;
    float mx = fmaxf(fmaxf(v0, v1), v2);
#pragma unroll
    for (int o = 16; o; o >>= 1) mx = fmaxf(mx, __shfl_xor_sync(0xffffffffu, mx, o));
    __shared__ float sm[4];
    if ((tid & 31) == 0) sm[tid >> 5] = mx;
    __syncthreads();
    mx = fmaxf(fmaxf(sm[0], sm[1]), fmaxf(sm[2], sm[3]));
    float e0 = __expf(v0 - mx), e1 = __expf(v1 - mx);
    float e2 = (tid < 4) ? __expf(v2 - mx) : 0.f;
    float s = e0 + e1 + e2;
#pragma unroll
    for (int o = 16; o; o >>= 1) s += __shfl_xor_sync(0xffffffffu, s, o);
    __shared__ float sq[4];
    if ((tid & 31) == 0) sq[tid >> 5] = s;
    __syncthreads();
    s = sq[0] + sq[1] + sq[2] + sq[3];
    float inv = __fdividef(1.f, s);
    ph[tid]       = __float2half_rn(e0 * inv);
    ph[tid + 128] = __float2half_rn(e1 * inv);
    if (tid < 4)  ph[tid + 256] = __float2half_rn(e2 * inv);
    if (tid >= 4 && tid < 16) ph[tid + 256] = __float2half_rn(0.f);
}

// ---------------- w = softmax(mean(tok[:, :4]) @ mk^T / sqrt(D)) ----------------
__global__ void __launch_bounds__(256) compute_w_kernel(
    const float* __restrict__ tok, const float* __restrict__ mk,
    float* __restrict__ wout)
{
    int tid = threadIdx.x;
    int p = tid >> 3;
    int b = p >> 3, m = p & 7;
    int j = tid & 7;
    const float* tb = tok + (size_t)b * TT * DD;
    const float* key = mk + (size_t)m * DD;
    float acc = 0.f;
    for (int d = j * 4; d < DD; d += 32) {
        float4 k4 = *(const float4*)(key + d);
        float4 t0 = *(const float4*)(tb + d);
        float4 t1 = *(const float4*)(tb + DD + d);
        float4 t2 = *(const float4*)(tb + 2 * DD + d);
        float4 t3 = *(const float4*)(tb + 3 * DD + d);
        acc = fmaf(0.25f * (t0.x + t1.x + t2.x + t3.x), k4.x, acc);
        acc = fmaf(0.25f * (t0.y + t1.y + t2.y + t3.y), k4.y, acc);
        acc = fmaf(0.25f * (t0.z + t1.z + t2.z + t3.z), k4.z, acc);
        acc = fmaf(0.25f * (t0.w + t1.w + t2.w + t3.w), k4.w, acc);
    }
    acc += __shfl_xor_sync(0xffffffffu, acc, 4);
    acc += __shfl_xor_sync(0xffffffffu, acc, 2);
    acc += __shfl_xor_sync(0xffffffffu, acc, 1);
    __shared__ float sl[32];
    if (j == 0) sl[p] = acc * 0.05103103630798288f;
    __syncthreads();
    if (tid < 32) {
        float logit = sl[tid];
        float mx = logit;
#pragma unroll
        for (int o = 4; o; o >>= 1) mx = fmaxf(mx, __shfl_xor_sync(0xffffffffu, mx, o));
        float e = __expf(logit - mx);
        float s = e;
#pragma unroll
        for (int o = 4; o; o >>= 1) s += __shfl_xor_sync(0xffffffffu, s, o);
        wout[tid] = e / s;
    }
}

// ---------------- hard-concrete via HW tanh ----------------
__device__ __forceinline__ float hc_z(float u, float la)
{
    u = fminf(fmaxf(u, 1e-6f), 1.0f - 1e-6f);
    float t = (__logf(u) - __logf(1.0f - u) + la) * 0.75f;
    float z = fmaf(0.6f, tanh_fast(t), 0.5f);
    return fminf(fmaxf(z, 0.0f), 1.0f);
}

// ---------------- fused delta: 1 group/thread (at HBM roof — frozen) ----------------
__global__ void __launch_bounds__(256) delta_kernel(
    const float* __restrict__ u_a, const float* __restrict__ la_a, const float* __restrict__ phi_a,
    const float* __restrict__ u_b, const float* __restrict__ la_b, const float* __restrict__ phi_b,
    const float* __restrict__ wbuf, float* __restrict__ out)
{
    __shared__ float ws[32];
    if (threadIdx.x < 32) ws[threadIdx.x] = wbuf[threadIdx.x];
    __syncthreads();

    int g = blockIdx.x * 256 + threadIdx.x;
    bool isB = g >= GCNT;
    int gg = isB ? g - GCNT : g;
    const float* up = isB ? u_b : u_a;
    const float* lp = isB ? la_b : la_a;
    const float* pp = isB ? phi_b : phi_a;

    size_t e8 = (size_t)gg * 8;
    float4 u0 = __ldcs((const float4*)(up + e8));
    float4 u1 = __ldcs((const float4*)(up + e8 + 4));
    float4 l0 = __ldcs((const float4*)(lp + e8));
    float4 l1 = __ldcs((const float4*)(lp + e8 + 4));
    float phi = __ldcs(pp + gg);

    float z[8];
    z[0] = hc_z(u0.x, l0.x); z[1] = hc_z(u0.y, l0.y);
    z[2] = hc_z(u0.z, l0.z); z[3] = hc_z(u0.w, l0.w);
    z[4] = hc_z(u1.x, l1.x); z[5] = hc_z(u1.y, l1.y);
    z[6] = hc_z(u1.z, l1.z); z[7] = hc_z(u1.w, l1.w);

    size_t base = (size_t)(isB ? GCNT : 0) + (size_t)gg;
#pragma unroll
    for (int b = 0; b < 4; b++) {
        float acc = 0.f;
#pragma unroll
        for (int m = 0; m < 8; m++) acc = fmaf(z[m], ws[b * 8 + m], acc);
        __stcs(out + (size_t)b * OUTROW + base, acc * phi);
    }
}

// ---------------- host launch ----------------
extern "C" void kernel_launch(void* const* d_in, const int* in_sizes, int n_in,
                              void* d_out, int out_size)
{
    const float* x      = (const float*)d_in[0];
    const float* u_a    = (const float*)d_in[1];
    const float* u_b    = (const float*)d_in[2];
    const float* phi_a  = (const float*)d_in[3];
    const float* phi_b  = (const float*)d_in[4];
    const float* la_a   = (const float*)d_in[5];
    const float* la_b   = (const float*)d_in[6];
    const float* Wp     = (const float*)d_in[7];
    const float* bp     = (const float*)d_in[8];
    const float* skills = (const float*)d_in[9];
    const float* cenc   = (const float*)d_in[10];
    const float* ln1_g  = (const float*)d_in[11];
    const float* ln1_b  = (const float*)d_in[12];
    const float* Wqkv   = (const float*)d_in[13];
    const float* bqkv   = (const float*)d_in[14];
    const float* Wo     = (const float*)d_in[15];
    const float* bo     = (const float*)d_in[16];
    const float* ln2_g  = (const float*)d_in[17];
    const float* ln2_b  = (const float*)d_in[18];
    const float* W1     = (const float*)d_in[19];
    const float* b1     = (const float*)d_in[20];
    const float* W2     = (const float*)d_in[21];
    const float* b2     = (const float*)d_in[22];
    const float* mk     = (const float*)d_in[23];
    float* out = (float*)d_out;

    float* scratch = nullptr;
    cudaGetSymbolAddress((void**)&scratch, g_scratch);
    __half* hbuf = nullptr;
    cudaGetSymbolAddress((void**)&hbuf, g_half);

    float* tok  = scratch + OFF_TOK;
    float* sc   = scratch + OFF_SC;
    float* ob   = scratch + OFF_O;
    float* wbuf = scratch + OFF_W;

    const __half* hx    = hbuf + HX_OFF;
    const __half* hWp   = hbuf + HWP_OFF;
    const __half* hWqkv = hbuf + HWQKV_OFF;
    const __half* hWo   = hbuf + HWO_OFF;
    const __half* hW1   = hbuf + HW1_OFF;
    const __half* hW2   = hbuf + HW2_OFF;
    const __half* hq    = hbuf + HQ_OFF;
    const __half* hkT   = hbuf + HKT_OFF;
    const __half* hv    = hbuf + HV_OFF;
    const __half* hpr   = hbuf + HPR_OFF;
    __half* hy  = hbuf + HY_OFF;
    __half* hob = hbuf + HOB_OFF;
    __half* hff = hbuf + HFF_OFF;

    // 0. convert x + weights to fp16, and fill skill tokens
    conv_kernel<<<(CONV_N + BB * 4 * DD + 255) / 256, 256>>>(
        x, Wp, Wqkv, Wo, W1, W2, skills, tok);

    // 1. h = x@Wp + bp + count_enc -> tok rows [4:260)
    hgemm_kernel<64><<<dim3(DD / 64, (NN + 63) / 64, BB), 256>>>(
        hx, hWp, bp, cenc, tok + 4 * DD, nullptr,
        NN, DD, DD, DD, DD, DD,
        (long long)NN * DD, 0LL, (long long)TT * DD, 0LL, 1,
        DD, 1.0f, 2);

    // 2. LN1 -> half y
    ln_kernel<<<ROWS / 8, 256>>>(tok, ln1_g, ln1_b, hy);

    // 3. qkv = y @ Wqkv + bqkv -> scattered half q / kT / v  (wide: BN=128)
    hgemm_kernel<128><<<dim3(3 * DD / 128, (ROWS + 63) / 64, 1), 256>>>(
        hy, hWqkv, bqkv, nullptr, nullptr, nullptr,
        ROWS, 3 * DD, DD, DD, 3 * DD, 3 * DD,
        0LL, 0LL, 0LL, 0LL, 1,
        0, 1.0f, 4);

    // 4. scores = q @ kT / sqrt(96)  (batched over BH=16, BN=128)
    hgemm_kernel<128><<<dim3((TT + 127) / 128, (TT + 63) / 64, BB * HH), 256>>>(
        hq, hkT, nullptr, nullptr, sc, nullptr,
        TT, TT, DH, DH, TTP, TTP,
        (long long)TT * DH, (long long)DH * TTP, (long long)TT * TT, 0LL, 1,
        TT, 0.10206207261596577f, 0);

    // 5. softmax -> half probs (stride 272, zero tail)
    softmax260_kernel<<<BB * HH * TT, 128>>>(sc, hbuf + HPR_OFF);

    // 6. o = probs @ v -> fp32 ob (B,T,D) + half mirror
    hgemm_kernel<64><<<dim3((DH + 63) / 64, (TT + 63) / 64, BB * HH), 256>>>(
        hpr, hv, nullptr, nullptr, ob, hob,
        TT, DH, TTP, TTP, DH, DH,
        (long long)TT * TTP, (long long)TTP * DH,
        (long long)TT * DD, (long long)DH, HH,
        DD, 1.0f, 0);

    // 7. tok += o @ Wo + bo
    hgemm_kernel<64><<<dim3(DD / 64, (ROWS + 63) / 64, 1), 256>>>(
        hob, hWo, bo, tok, tok, nullptr,
        ROWS, DD, DD, DD, DD, DD,
        0LL, 0LL, 0LL, 0LL, 1,
        DD, 1.0f, 3);

    // 8. LN2 -> half y
    ln_kernel<<<ROWS / 8, 256>>>(tok, ln2_g, ln2_b, hy);

    // 9. ff = gelu(y @ W1 + b1) -> half only  (wide: BN=128)
    hgemm_kernel<128><<<dim3(2 * DD / 128, (ROWS + 63) / 64, 1), 256>>>(
        hy, hW1, b1, nullptr, nullptr, hff,
        ROWS, 2 * DD, DD, DD, 2 * DD, 2 * DD,
        0LL, 0LL, 0LL, 0LL, 1,
        2 * DD, 1.0f, 1);

    // 10. tok += ff @ W2 + b2
    hgemm_kernel<64><<<dim3(DD / 64, (ROWS + 63) / 64, 1), 256>>>(
        hff, hW2, b2, tok, tok, nullptr,
        ROWS, DD, 2 * DD, 2 * DD, DD, DD,
        0LL, 0LL, 0LL, 0LL, 1,
        DD, 1.0f, 3);

    // 11. w
    compute_w_kernel<<<1, 256>>>(tok, mk, wbuf);

    // 12. fused hard-concrete + contraction
    delta_kernel<<<(2 * GCNT) / 256, 256>>>(
        u_a, la_a, phi_a, u_b, la_b, phi_b, wbuf, out);
}

// round 16
// speedup vs baseline: 1.0140x; 1.0140x over previous
#include <cuda_runtime.h>
#include <cuda_fp16.h>
#include <cstdint>
#include <math.h>

// ---------------- problem constants ----------------
#define BB   4
#define NN   256
#define DD   384
#define LL   12
#define F1C  1536
#define F2C  384
#define MM   8
#define HH   4
#define TT   260          // 4 skill tokens + 256
#define DH   96           // D / H
#define ROWS (BB*TT)      // 1040
#define TTP  272          // TT padded to multiple of 16

#define GCNT   (LL*F1C*F2C)          // 7,077,888 groups per side
#define OUTROW (2LL*GCNT)

// ---------------- fp32 scratch ----------------
#define OFF_TOK  0
#define SZ_TOK   (ROWS*DD)
#define OFF_SC   (OFF_TOK + SZ_TOK)
#define SZ_SC    (BB*HH*TT*TT)
#define OFF_O    (OFF_SC + SZ_SC)
#define SZ_O     (ROWS*DD)
#define OFF_W    (OFF_O + SZ_O)
#define SZ_W     32
#define SCRATCH_TOTAL (OFF_W + SZ_W)
__device__ float g_scratch[SCRATCH_TOTAL];

// ---------------- fp16 scratch (offsets in halves) ----------------
#define HX_OFF     0
#define HWP_OFF    393216
#define HWQKV_OFF  540672
#define HWO_OFF    983040
#define HW1_OFF    1130496
#define HW2_OFF    1425408
#define HQ_OFF     1720320
#define HKT_OFF    2119680
#define HV_OFF     2537472
#define HPR_OFF    2955264
#define HY_OFF     4086784
#define HOB_OFF    4486144
#define HFF_OFF    4885504
#define HTOTAL     5684224
__device__ __half g_half[HTOTAL];

__device__ __forceinline__ float tanh_fast(float x)
{
    float r;
    asm("tanh.approx.f32 %0, %1;" : "=f"(r) : "f"(x));
    return r;
}

__device__ __forceinline__ void cp16(void* smem, const void* gmem, bool pred)
{
    unsigned int saddr = (unsigned int)__cvta_generic_to_shared(smem);
    int sz = pred ? 16 : 0;
    asm volatile("cp.async.cg.shared.global [%0], [%1], 16, %2;"
                 :: "r"(saddr), "l"(gmem), "r"(sz) : "memory");
}

// ---------------- fp32 -> fp16 conversion (vectorized) + skill-token fill ----------------
#define CONV_V4 430080                 // 1720320 / 4 float4s
__global__ void conv_kernel(const float* __restrict__ x,  const float* __restrict__ Wp,
                            const float* __restrict__ Wqkv, const float* __restrict__ Wo,
                            const float* __restrict__ W1, const float* __restrict__ W2,
                            const float* __restrict__ skills, float* __restrict__ tok)
{
    int i = blockIdx.x * 256 + threadIdx.x;
    if (i >= CONV_V4) {
        int i2 = i - CONV_V4;
        if (i2 < BB * 4 * DD) {
            int b = i2 / (4 * DD);
            int r = i2 % (4 * DD);
            tok[(size_t)(b * TT) * DD + r] = skills[r];
        }
        return;
    }
    int e = i * 4;
    const float* src;
    if      (e < 393216)  src = x + e;
    else if (e < 540672)  src = Wp + (e - 393216);
    else if (e < 983040)  src = Wqkv + (e - 540672);
    else if (e < 1130496) src = Wo + (e - 983040);
    else if (e < 1425408) src = W1 + (e - 1130496);
    else                  src = W2 + (e - 1425408);
    float4 v = *(const float4*)src;
    __half2 h0 = __floats2half2_rn(v.x, v.y);
    __half2 h1 = __floats2half2_rn(v.z, v.w);
    uint2 pk;
    pk.x = *(unsigned int*)&h0;
    pk.y = *(unsigned int*)&h1;
    *(uint2*)(g_half + e) = pk;
}

// ---------------- epilogue helper ----------------
// epi: 0=none, 1=gelu->half only, 2=+R[col], 3=+Rm residual, 4=qkv scatter
__device__ __forceinline__ void epi_store2(
    float v0, float v1, int row, int col, int Mr, int N,
    const float* bias, const float* R, const float* Rm,
    float* C, __half* hC, int ldc, float scale, int epi)
{
    if (row >= Mr || col >= N) return;
    float b0 = 0.f, b1 = 0.f;
    if (bias) { b0 = bias[col]; b1 = bias[col + 1]; }
    v0 = v0 * scale + b0;
    v1 = v1 * scale + b1;
    if (epi == 1) {
        float t;
        t = v0; v0 = 0.5f * t * (1.f + tanh_fast(0.7978845608028654f * (t + 0.044715f * t * t * t)));
        t = v1; v1 = 0.5f * t * (1.f + tanh_fast(0.7978845608028654f * (t + 0.044715f * t * t * t)));
    } else if (epi == 2) {
        v0 += R[col]; v1 += R[col + 1];
    } else if (epi == 3) {
        const float* rr = Rm + (size_t)row * ldc + col;
        v0 += rr[0]; v1 += rr[1];
    }
    if (epi == 4) {
        int b = row / TT, t = row - b * TT;
        int s = col / DD;
        int rem = col - s * DD;
        int h = rem / DH;
        int d = rem - h * DH;
        int bh = b * HH + h;
        if (s == 0) {
            *(__half2*)(g_half + HQ_OFF + ((size_t)(bh * TT + t)) * DH + d) =
                __floats2half2_rn(v0, v1);
        } else if (s == 1) {
            g_half[HKT_OFF + ((size_t)(bh * DH + d)) * TTP + t]     = __float2half_rn(v0);
            g_half[HKT_OFF + ((size_t)(bh * DH + d + 1)) * TTP + t] = __float2half_rn(v1);
        } else {
            *(__half2*)(g_half + HV_OFF + ((size_t)(bh * TTP + t)) * DH + d) =
                __floats2half2_rn(v0, v1);
        }
        return;
    }
    if (C)  *(float2*)(C + (size_t)row * ldc + col) = make_float2(v0, v1);
    if (hC) *(__half2*)(hC + (size_t)row * ldc + col) = __floats2half2_rn(v0, v1);
}

// ---------------- fp16 tensor-core GEMM: CTA 64x64, K-slab 32, 4-stage cp.async ----------------
__global__ void __launch_bounds__(256) hgemm_kernel(
    const __half* __restrict__ A, const __half* __restrict__ B,
    const float* __restrict__ bias, const float* __restrict__ R,
    float* __restrict__ C, __half* __restrict__ hC,
    int Mr, int N, int K, int lda, int ldb, int Nload,
    long long aBS, long long wBS, long long cBS1, long long cBS2, int cdiv,
    int ldc, float scale, int epi)
{
    int z = blockIdx.z;
    A += (size_t)z * aBS;
    B += (size_t)z * wBS;
    size_t coff = (size_t)(z / cdiv) * cBS1 + (size_t)(z % cdiv) * cBS2;
    if (C)  C += coff;
    if (hC) hC += coff;
    const float* Rm = (epi == 3) ? (R + coff) : nullptr;

    __shared__ __half As[4][64][40];
    __shared__ __half Bs[4][32][72];

    int bm = blockIdx.y * 64, bn = blockIdx.x * 64;
    int tid = threadIdx.x;
    int lane = tid & 31, warp = tid >> 5;
    int wm = warp >> 1, wn = warp & 1;

    int ar = tid >> 2;
    int ac = (tid & 3) << 3;
    int arow = bm + ar;
    bool a_row_ok = arow < Mr;
    const __half* Ap = A + (size_t)(a_row_ok ? arow : 0) * lda + ac;

    int br = tid >> 3;
    int bc = (tid & 7) << 3;
    bool b_col_ok = (bn + bc) < Nload;
    const __half* Bp = B + (size_t)br * ldb + (b_col_ok ? bn + bc : 0);

    float acc[4][4];
#pragma unroll
    for (int nt = 0; nt < 4; nt++)
#pragma unroll
        for (int i = 0; i < 4; i++) acc[nt][i] = 0.f;

    // prologue: issue slabs 0..2 into stages 0..2
#pragma unroll
    for (int s = 0; s < 3; s++) {
        int k0 = s * 32;
        bool pa = a_row_ok && (k0 + ac) < K;
        bool pb = b_col_ok && (k0 + br) < K;
        cp16(&As[s][ar][ac], pa ? (Ap + k0) : Ap, pa);
        cp16(&Bs[s][br][bc], pb ? (Bp + (size_t)k0 * ldb) : Bp, pb);
        asm volatile("cp.async.commit_group;" ::: "memory");
    }

    int lb = lane >> 3, lr = lane & 7;
    int frag_row = (lb & 1) * 8 + lr;
    int frag_col = (lb >> 1) * 8;

    int cur = 0;
    for (int k0 = 0; k0 < K; k0 += 32) {
        asm volatile("cp.async.wait_group 2;" ::: "memory");
        __syncthreads();

        // issue slab k0+96 into stage (cur+3)&3
        {
            int kn = k0 + 96;
            int nst = (cur + 3) & 3;
            bool pa = a_row_ok && (kn + ac) < K;
            bool pb = b_col_ok && (kn + br) < K;
            cp16(&As[nst][ar][ac], pa ? (Ap + kn) : Ap, pa);
            cp16(&Bs[nst][br][bc], pb ? (Bp + (size_t)kn * ldb) : Bp, pb);
            asm volatile("cp.async.commit_group;" ::: "memory");
        }

        unsigned int afr[2][4];
        unsigned int bfr[2][4][2];
#pragma unroll
        for (int kk = 0; kk < 2; kk++) {
            unsigned int addr = (unsigned int)__cvta_generic_to_shared(
                &As[cur][wm * 16 + frag_row][kk * 16 + frag_col]);
            asm volatile("ldmatrix.sync.aligned.m8n8.x4.shared.b16 {%0,%1,%2,%3}, [%4];"
                : "=r"(afr[kk][0]), "=r"(afr[kk][1]), "=r"(afr[kk][2]), "=r"(afr[kk][3])
                : "r"(addr));
        }
#pragma unroll
        for (int kk = 0; kk < 2; kk++)
#pragma unroll
            for (int p = 0; p < 2; p++) {
                unsigned int addr = (unsigned int)__cvta_generic_to_shared(
                    &Bs[cur][kk * 16 + frag_row][wn * 32 + p * 16 + frag_col]);
                asm volatile("ldmatrix.sync.aligned.m8n8.x4.trans.shared.b16 {%0,%1,%2,%3}, [%4];"
                    : "=r"(bfr[kk][p * 2][0]), "=r"(bfr[kk][p * 2][1]),
                      "=r"(bfr[kk][p * 2 + 1][0]), "=r"(bfr[kk][p * 2 + 1][1])
                    : "r"(addr));
            }
#pragma unroll
        for (int kk = 0; kk < 2; kk++)
#pragma unroll
            for (int nt = 0; nt < 4; nt++) {
                asm volatile(
                    "mma.sync.aligned.m16n8k16.row.col.f32.f16.f16.f32 "
                    "{%0,%1,%2,%3}, {%4,%5,%6,%7}, {%8,%9}, {%0,%1,%2,%3};"
                    : "+f"(acc[nt][0]), "+f"(acc[nt][1]),
                      "+f"(acc[nt][2]), "+f"(acc[nt][3])
                    : "r"(afr[kk][0]), "r"(afr[kk][1]), "r"(afr[kk][2]), "r"(afr[kk][3]),
                      "r"(bfr[kk][nt][0]), "r"(bfr[kk][nt][1]));
            }

        cur = (cur + 1) & 3;
    }

    int g = lane >> 2, t2 = (lane & 3) << 1;
    int row0 = bm + wm * 16 + g;
#pragma unroll
    for (int nt = 0; nt < 4; nt++) {
        int col = bn + wn * 32 + nt * 8 + t2;
        epi_store2(acc[nt][0], acc[nt][1], row0,     col, Mr, N,
                   bias, R, Rm, C, hC, ldc, scale, epi);
        epi_store2(acc[nt][2], acc[nt][3], row0 + 8, col, Mr, N,
                   bias, R, Rm, C, hC, ldc, scale, epi);
    }
}

// ---------------- layernorm: 1 warp/row, 8 rows/block, barrier-free ----------------
__global__ void __launch_bounds__(256) ln_kernel(
    const float* __restrict__ X, const float* __restrict__ gw,
    const float* __restrict__ bw, __half* __restrict__ Y)
{
    int warp = threadIdx.x >> 5;
    int lane = threadIdx.x & 31;
    int row = blockIdx.x * 8 + warp;
    const float* x = X + (size_t)row * DD;

    float4 v[3];
    float s = 0.f, q = 0.f;
#pragma unroll
    for (int k = 0; k < 3; k++) {
        v[k] = *(const float4*)(x + lane * 4 + k * 128);
        s += v[k].x + v[k].y + v[k].z + v[k].w;
        q += v[k].x * v[k].x + v[k].y * v[k].y + v[k].z * v[k].z + v[k].w * v[k].w;
    }
#pragma unroll
    for (int o = 16; o; o >>= 1) {
        s += __shfl_xor_sync(0xffffffffu, s, o);
        q += __shfl_xor_sync(0xffffffffu, q, o);
    }
    float mean = s * (1.f / DD);
    float var = q * (1.f / DD) - mean * mean;
    float inv = rsqrtf(var + 1e-6f);

    __half* y = Y + (size_t)row * DD;
#pragma unroll
    for (int k = 0; k < 3; k++) {
        int d = lane * 4 + k * 128;
        float4 g4 = *(const float4*)(gw + d);
        float4 b4 = *(const float4*)(bw + d);
        float r0 = (v[k].x - mean) * inv * g4.x + b4.x;
        float r1 = (v[k].y - mean) * inv * g4.y + b4.y;
        float r2 = (v[k].z - mean) * inv * g4.z + b4.z;
        float r3 = (v[k].w - mean) * inv * g4.w + b4.w;
        __half2 h0 = __floats2half2_rn(r0, r1);
        __half2 h1 = __floats2half2_rn(r2, r3);
        uint2 pk;
        pk.x = *(unsigned int*)&h0;
        pk.y = *(unsigned int*)&h1;
        *(uint2*)(y + d) = pk;
    }
}

// ---------------- softmax over 260 cols: fp32 scores -> half probs (stride 272) ----------------
__global__ void __launch_bounds__(128) softmax260_kernel(
    const float* __restrict__ S, __half* __restrict__ P)
{
    int row = blockIdx.x;
    const float* p = S + (size_t)row * TT;
    __half* ph = P + (size_t)row * TTP;
    int tid = threadIdx.x;
    float v0 = p[tid], v1 = p[tid + 128];
    float v2 = (tid < 4) ? p[tid + 256] : -1e30f;
    float mx = fmaxf(fmaxf(v0, v1), v2);
#pragma unroll
    for (int o = 16; o; o >>= 1) mx = fmaxf(mx, __shfl_xor_sync(0xffffffffu, mx, o));
    __shared__ float sm[4];
    if ((tid & 31) == 0) sm[tid >> 5] = mx;
    __syncthreads();
    mx = fmaxf(fmaxf(sm[0], sm[1]), fmaxf(sm[2], sm[3]));
    float e0 = __expf(v0 - mx), e1 = __expf(v1 - mx);
    float e2 = (tid < 4) ? __expf(v2 - mx) : 0.f;
    float s = e0 + e1 + e2;
#pragma unroll
    for (int o = 16; o; o >>= 1) s += __shfl_xor_sync(0xffffffffu, s, o);
    __shared__ float sq[4];
    if ((tid & 31) == 0) sq[tid >> 5] = s;
    __syncthreads();
    s = sq[0] + sq[1] + sq[2] + sq[3];
    float inv = __fdividef(1.f, s);
    ph[tid]       = __float2half_rn(e0 * inv);
    ph[tid + 128] = __float2half_rn(e1 * inv);
    if (tid < 4)  ph[tid + 256] = __float2half_rn(e2 * inv);
    if (tid >= 4 && tid < 16) ph[tid + 256] = __float2half_rn(0.f);
}

// ---------------- w = softmax(mean(tok[:, :4]) @ mk^T / sqrt(D)) ----------------
__global__ void __launch_bounds__(256) compute_w_kernel(
    const float* __restrict__ tok, const float* __restrict__ mk,
    float* __restrict__ wout)
{
    int tid = threadIdx.x;
    int p = tid >> 3;
    int b = p >> 3, m = p & 7;
    int j = tid & 7;
    const float* tb = tok + (size_t)b * TT * DD;
    const float* key = mk + (size_t)m * DD;
    float acc = 0.f;
    for (int d = j * 4; d < DD; d += 32) {
        float4 k4 = *(const float4*)(key + d);
        float4 t0 = *(const float4*)(tb + d);
        float4 t1 = *(const float4*)(tb + DD + d);
        float4 t2 = *(const float4*)(tb + 2 * DD + d);
        float4 t3 = *(const float4*)(tb + 3 * DD + d);
        acc = fmaf(0.25f * (t0.x + t1.x + t2.x + t3.x), k4.x, acc);
        acc = fmaf(0.25f * (t0.y + t1.y + t2.y + t3.y), k4.y, acc);
        acc = fmaf(0.25f * (t0.z + t1.z + t2.z + t3.z), k4.z, acc);
        acc = fmaf(0.25f * (t0.w + t1.w + t2.w + t3.w), k4.w, acc);
    }
    acc += __shfl_xor_sync(0xffffffffu, acc, 4);
    acc += __shfl_xor_sync(0xffffffffu, acc, 2);
    acc += __shfl_xor_sync(0xffffffffu, acc, 1);
    __shared__ float sl[32];
    if (j == 0) sl[p] = acc * 0.05103103630798288f;
    __syncthreads();
    if (tid < 32) {
        float logit = sl[tid];
        float mx = logit;
#pragma unroll
        for (int o = 4; o; o >>= 1) mx = fmaxf(mx, __shfl_xor_sync(0xffffffffu, mx, o));
        float e = __expf(logit - mx);
        float s = e;
#pragma unroll
        for (int o = 4; o; o >>= 1) s += __shfl_xor_sync(0xffffffffu, s, o);
        wout[tid] = e / s;
    }
}

// ---------------- hard-concrete via HW tanh ----------------
__device__ __forceinline__ float hc_z(float u, float la)
{
    u = fminf(fmaxf(u, 1e-6f), 1.0f - 1e-6f);
    float t = (__logf(u) - __logf(1.0f - u) + la) * 0.75f;
    float z = fmaf(0.6f, tanh_fast(t), 0.5f);
    return fminf(fmaxf(z, 0.0f), 1.0f);
}

// ---------------- fused delta: 1 group/thread (at HBM roof — frozen) ----------------
__global__ void __launch_bounds__(256) delta_kernel(
    const float* __restrict__ u_a, const float* __restrict__ la_a, const float* __restrict__ phi_a,
    const float* __restrict__ u_b, const float* __restrict__ la_b, const float* __restrict__ phi_b,
    const float* __restrict__ wbuf, float* __restrict__ out)
{
    __shared__ float ws[32];
    if (threadIdx.x < 32) ws[threadIdx.x] = wbuf[threadIdx.x];
    __syncthreads();

    int g = blockIdx.x * 256 + threadIdx.x;
    bool isB = g >= GCNT;
    int gg = isB ? g - GCNT : g;
    const float* up = isB ? u_b : u_a;
    const float* lp = isB ? la_b : la_a;
    const float* pp = isB ? phi_b : phi_a;

    size_t e8 = (size_t)gg * 8;
    float4 u0 = __ldcs((const float4*)(up + e8));
    float4 u1 = __ldcs((const float4*)(up + e8 + 4));
    float4 l0 = __ldcs((const float4*)(lp + e8));
    float4 l1 = __ldcs((const float4*)(lp + e8 + 4));
    float phi = __ldcs(pp + gg);

    float z[8];
    z[0] = hc_z(u0.x, l0.x); z[1] = hc_z(u0.y, l0.y);
    z[2] = hc_z(u0.z, l0.z); z[3] = hc_z(u0.w, l0.w);
    z[4] = hc_z(u1.x, l1.x); z[5] = hc_z(u1.y, l1.y);
    z[6] = hc_z(u1.z, l1.z); z[7] = hc_z(u1.w, l1.w);

    size_t base = (size_t)(isB ? GCNT : 0) + (size_t)gg;
#pragma unroll
    for (int b = 0; b < 4; b++) {
        float acc = 0.f;
#pragma unroll
        for (int m = 0; m < 8; m++) acc = fmaf(z[m], ws[b * 8 + m], acc);
        __stcs(out + (size_t)b * OUTROW + base, acc * phi);
    }
}

// ---------------- host launch ----------------
extern "C" void kernel_launch(void* const* d_in, const int* in_sizes, int n_in,
                              void* d_out, int out_size)
{
    const float* x      = (const float*)d_in[0];
    const float* u_a    = (const float*)d_in[1];
    const float* u_b    = (const float*)d_in[2];
    const float* phi_a  = (const float*)d_in[3];
    const float* phi_b  = (const float*)d_in[4];
    const float* la_a   = (const float*)d_in[5];
    const float* la_b   = (const float*)d_in[6];
    const float* Wp     = (const float*)d_in[7];
    const float* bp     = (const float*)d_in[8];
    const float* skills = (const float*)d_in[9];
    const float* cenc   = (const float*)d_in[10];
    const float* ln1_g  = (const float*)d_in[11];
    const float* ln1_b  = (const float*)d_in[12];
    const float* Wqkv   = (const float*)d_in[13];
    const float* bqkv   = (const float*)d_in[14];
    const float* Wo     = (const float*)d_in[15];
    const float* bo     = (const float*)d_in[16];
    const float* ln2_g  = (const float*)d_in[17];
    const float* ln2_b  = (const float*)d_in[18];
    const float* W1     = (const float*)d_in[19];
    const float* b1     = (const float*)d_in[20];
    const float* W2     = (const float*)d_in[21];
    const float* b2     = (const float*)d_in[22];
    const float* mk     = (const float*)d_in[23];
    float* out = (float*)d_out;

    float* scratch = nullptr;
    cudaGetSymbolAddress((void**)&scratch, g_scratch);
    __half* hbuf = nullptr;
    cudaGetSymbolAddress((void**)&hbuf, g_half);

    float* tok  = scratch + OFF_TOK;
    float* sc   = scratch + OFF_SC;
    float* ob   = scratch + OFF_O;
    float* wbuf = scratch + OFF_W;

    const __half* hx    = hbuf + HX_OFF;
    const __half* hWp   = hbuf + HWP_OFF;
    const __half* hWqkv = hbuf + HWQKV_OFF;
    const __half* hWo   = hbuf + HWO_OFF;
    const __half* hW1   = hbuf + HW1_OFF;
    const __half* hW2   = hbuf + HW2_OFF;
    const __half* hq    = hbuf + HQ_OFF;
    const __half* hkT   = hbuf + HKT_OFF;
    const __half* hv    = hbuf + HV_OFF;
    const __half* hpr   = hbuf + HPR_OFF;
    __half* hy  = hbuf + HY_OFF;
    __half* hob = hbuf + HOB_OFF;
    __half* hff = hbuf + HFF_OFF;

    // 0. convert x + weights to fp16 (vectorized), and fill skill tokens
    conv_kernel<<<(CONV_V4 + BB * 4 * DD + 255) / 256, 256>>>(
        x, Wp, Wqkv, Wo, W1, W2, skills, tok);

    // 1. h = x@Wp + bp + count_enc -> tok rows [4:260)
    hgemm_kernel<<<dim3(DD / 64, (NN + 63) / 64, BB), 256>>>(
        hx, hWp, bp, cenc, tok + 4 * DD, nullptr,
        NN, DD, DD, DD, DD, DD,
        (long long)NN * DD, 0LL, (long long)TT * DD, 0LL, 1,
        DD, 1.0f, 2);

    // 2. LN1 -> half y
    ln_kernel<<<ROWS / 8, 256>>>(tok, ln1_g, ln1_b, hy);

    // 3. qkv = y @ Wqkv + bqkv -> scattered half q / kT / v
    hgemm_kernel<<<dim3(3 * DD / 64, (ROWS + 63) / 64, 1), 256>>>(
        hy, hWqkv, bqkv, nullptr, nullptr, nullptr,
        ROWS, 3 * DD, DD, DD, 3 * DD, 3 * DD,
        0LL, 0LL, 0LL, 0LL, 1,
        0, 1.0f, 4);

    // 4. scores = q @ kT / sqrt(96)  (batched over BH=16)
    hgemm_kernel<<<dim3((TT + 63) / 64, (TT + 63) / 64, BB * HH), 256>>>(
        hq, hkT, nullptr, nullptr, sc, nullptr,
        TT, TT, DH, DH, TTP, TTP,
        (long long)TT * DH, (long long)DH * TTP, (long long)TT * TT, 0LL, 1,
        TT, 0.10206207261596577f, 0);

    // 5. softmax -> half probs (stride 272, zero tail)
    softmax260_kernel<<<BB * HH * TT, 128>>>(sc, hbuf + HPR_OFF);

    // 6. o = probs @ v -> fp32 ob (B,T,D) + half mirror
    hgemm_kernel<<<dim3((DH + 63) / 64, (TT + 63) / 64, BB * HH), 256>>>(
        hpr, hv, nullptr, nullptr, ob, hob,
        TT, DH, TTP, TTP, DH, DH,
        (long long)TT * TTP, (long long)TTP * DH,
        (long long)TT * DD, (long long)DH, HH,
        DD, 1.0f, 0);

    // 7. tok += o @ Wo + bo
    hgemm_kernel<<<dim3(DD / 64, (ROWS + 63) / 64, 1), 256>>>(
        hob, hWo, bo, tok, tok, nullptr,
        ROWS, DD, DD, DD, DD, DD,
        0LL, 0LL, 0LL, 0LL, 1,
        DD, 1.0f, 3);

    // 8. LN2 -> half y
    ln_kernel<<<ROWS / 8, 256>>>(tok, ln2_g, ln2_b, hy);

    // 9. ff = gelu(y @ W1 + b1) -> half only
    hgemm_kernel<<<dim3(2 * DD / 64, (ROWS + 63) / 64, 1), 256>>>(
        hy, hW1, b1, nullptr, nullptr, hff,
        ROWS, 2 * DD, DD, DD, 2 * DD, 2 * DD,
        0LL, 0LL, 0LL, 0LL, 1,
        2 * DD, 1.0f, 1);

    // 10. tok += ff @ W2 + b2
    hgemm_kernel<<<dim3(DD / 64, (ROWS + 63) / 64, 1), 256>>>(
        hff, hW2, b2, tok, tok, nullptr,
        ROWS, DD, 2 * DD, 2 * DD, DD, DD,
        0LL, 0LL, 0LL, 0LL, 1,
        DD, 1.0f, 3);

    // 11. w
    compute_w_kernel<<<1, 256>>>(tok, mk, wbuf);

    // 12. fused hard-concrete + contraction
    delta_kernel<<<(2 * GCNT) / 256, 256>>>(
        u_a, la_a, phi_a, u_b, la_b, phi_b, wbuf, out);
}

// round 17
// speedup vs baseline: 1.0174x; 1.0034x over previous
#include <cuda_runtime.h>
#include <cuda_fp16.h>
#include <cstdint>
#include <math.h>

// ---------------- problem constants ----------------
#define BB   4
#define NN   256
#define DD   384
#define LL   12
#define F1C  1536
#define F2C  384
#define MM   8
#define HH   4
#define TT   260          // 4 skill tokens + 256
#define DH   96           // D / H
#define ROWS (BB*TT)      // 1040
#define TTP  272          // TT padded to multiple of 16

#define GCNT   (LL*F1C*F2C)          // 7,077,888 groups per side
#define OUTROW (2LL*GCNT)

// ---------------- fp32 scratch ----------------
#define OFF_TOK  0
#define SZ_TOK   (ROWS*DD)
#define OFF_SC   (OFF_TOK + SZ_TOK)
#define SZ_SC    (BB*HH*TT*TT)
#define OFF_O    (OFF_SC + SZ_SC)
#define SZ_O     (ROWS*DD)
#define OFF_W    (OFF_O + SZ_O)
#define SZ_W     32
#define SCRATCH_TOTAL (OFF_W + SZ_W)
__device__ float g_scratch[SCRATCH_TOTAL];

// ---------------- fp16 scratch (offsets in halves) ----------------
#define HX_OFF     0
#define HWP_OFF    393216
#define HWQKV_OFF  540672
#define HWO_OFF    983040
#define HW1_OFF    1130496
#define HW2_OFF    1425408
#define HQ_OFF     1720320
#define HKT_OFF    2119680
#define HV_OFF     2537472
#define HPR_OFF    2955264
#define HY_OFF     4086784
#define HOB_OFF    4486144
#define HFF_OFF    4885504
#define HTOTAL     5684224
__device__ __half g_half[HTOTAL];

__device__ __forceinline__ float tanh_fast(float x)
{
    float r;
    asm("tanh.approx.f32 %0, %1;" : "=f"(r) : "f"(x));
    return r;
}

__device__ __forceinline__ void cp16(void* smem, const void* gmem, bool pred)
{
    unsigned int saddr = (unsigned int)__cvta_generic_to_shared(smem);
    int sz = pred ? 16 : 0;
    asm volatile("cp.async.cg.shared.global [%0], [%1], 16, %2;"
                 :: "r"(saddr), "l"(gmem), "r"(sz) : "memory");
}

// ---------------- fp32 -> fp16 conversion (vectorized) + skill-token fill ----------------
#define CONV_V4 430080                 // 1720320 / 4 float4s
__global__ void conv_kernel(const float* __restrict__ x,  const float* __restrict__ Wp,
                            const float* __restrict__ Wqkv, const float* __restrict__ Wo,
                            const float* __restrict__ W1, const float* __restrict__ W2,
                            const float* __restrict__ skills, float* __restrict__ tok)
{
    int i = blockIdx.x * 256 + threadIdx.x;
    if (i >= CONV_V4) {
        int i2 = i - CONV_V4;
        if (i2 < BB * 4 * DD) {
            int b = i2 / (4 * DD);
            int r = i2 % (4 * DD);
            tok[(size_t)(b * TT) * DD + r] = skills[r];
        }
        return;
    }
    int e = i * 4;
    const float* src;
    if      (e < 393216)  src = x + e;
    else if (e < 540672)  src = Wp + (e - 393216);
    else if (e < 983040)  src = Wqkv + (e - 540672);
    else if (e < 1130496) src = Wo + (e - 983040);
    else if (e < 1425408) src = W1 + (e - 1130496);
    else                  src = W2 + (e - 1425408);
    float4 v = *(const float4*)src;
    __half2 h0 = __floats2half2_rn(v.x, v.y);
    __half2 h1 = __floats2half2_rn(v.z, v.w);
    uint2 pk;
    pk.x = *(unsigned int*)&h0;
    pk.y = *(unsigned int*)&h1;
    *(uint2*)(g_half + e) = pk;
}

// ---------------- epilogue helper ----------------
// epi: 0=none, 1=gelu->half only, 2=+R[col], 3=+Rm residual, 4=qkv scatter
__device__ __forceinline__ void epi_store2(
    float v0, float v1, int row, int col, int Mr, int N,
    const float* bias, const float* R, const float* Rm,
    float* C, __half* hC, int ldc, float scale, int epi)
{
    if (row >= Mr || col >= N) return;
    float b0 = 0.f, b1 = 0.f;
    if (bias) { b0 = bias[col]; b1 = bias[col + 1]; }
    v0 = v0 * scale + b0;
    v1 = v1 * scale + b1;
    if (epi == 1) {
        float t;
        t = v0; v0 = 0.5f * t * (1.f + tanh_fast(0.7978845608028654f * (t + 0.044715f * t * t * t)));
        t = v1; v1 = 0.5f * t * (1.f + tanh_fast(0.7978845608028654f * (t + 0.044715f * t * t * t)));
    } else if (epi == 2) {
        v0 += R[col]; v1 += R[col + 1];
    } else if (epi == 3) {
        const float* rr = Rm + (size_t)row * ldc + col;
        v0 += rr[0]; v1 += rr[1];
    }
    if (epi == 4) {
        int b = row / TT, t = row - b * TT;
        int s = col / DD;
        int rem = col - s * DD;
        int h = rem / DH;
        int d = rem - h * DH;
        int bh = b * HH + h;
        if (s == 0) {
            *(__half2*)(g_half + HQ_OFF + ((size_t)(bh * TT + t)) * DH + d) =
                __floats2half2_rn(v0, v1);
        } else if (s == 1) {
            g_half[HKT_OFF + ((size_t)(bh * DH + d)) * TTP + t]     = __float2half_rn(v0);
            g_half[HKT_OFF + ((size_t)(bh * DH + d + 1)) * TTP + t] = __float2half_rn(v1);
        } else {
            *(__half2*)(g_half + HV_OFF + ((size_t)(bh * TTP + t)) * DH + d) =
                __floats2half2_rn(v0, v1);
        }
        return;
    }
    if (C)  *(float2*)(C + (size_t)row * ldc + col) = make_float2(v0, v1);
    if (hC) *(__half2*)(hC + (size_t)row * ldc + col) = __floats2half2_rn(v0, v1);
}

// ---------------- fp16 tensor-core GEMM: CTA 64x64, K-slab 32, 3-stage cp.async ----------------
__global__ void __launch_bounds__(256) hgemm_kernel(
    const __half* __restrict__ A, const __half* __restrict__ B,
    const float* __restrict__ bias, const float* __restrict__ R,
    float* __restrict__ C, __half* __restrict__ hC,
    int Mr, int N, int K, int lda, int ldb, int Nload,
    long long aBS, long long wBS, long long cBS1, long long cBS2, int cdiv,
    int ldc, float scale, int epi)
{
    int z = blockIdx.z;
    A += (size_t)z * aBS;
    B += (size_t)z * wBS;
    size_t coff = (size_t)(z / cdiv) * cBS1 + (size_t)(z % cdiv) * cBS2;
    if (C)  C += coff;
    if (hC) hC += coff;
    const float* Rm = (epi == 3) ? (R + coff) : nullptr;

    __shared__ __half As[3][64][40];
    __shared__ __half Bs[3][32][72];

    int bm = blockIdx.y * 64, bn = blockIdx.x * 64;
    int tid = threadIdx.x;
    int lane = tid & 31, warp = tid >> 5;
    int wm = warp >> 1, wn = warp & 1;

    int ar = tid >> 2;
    int ac = (tid & 3) << 3;
    int arow = bm + ar;
    bool a_row_ok = arow < Mr;
    const __half* Ap = A + (size_t)(a_row_ok ? arow : 0) * lda + ac;

    int br = tid >> 3;
    int bc = (tid & 7) << 3;
    bool b_col_ok = (bn + bc) < Nload;
    const __half* Bp = B + (size_t)br * ldb + (b_col_ok ? bn + bc : 0);

    float acc[4][4];
#pragma unroll
    for (int nt = 0; nt < 4; nt++)
#pragma unroll
        for (int i = 0; i < 4; i++) acc[nt][i] = 0.f;

    // prologue: issue slabs 0 and 1 into stages 0 and 1
#pragma unroll
    for (int s = 0; s < 2; s++) {
        int k0 = s * 32;
        bool pa = a_row_ok && (k0 + ac) < K;
        bool pb = b_col_ok && (k0 + br) < K;
        cp16(&As[s][ar][ac], pa ? (Ap + k0) : Ap, pa);
        cp16(&Bs[s][br][bc], pb ? (Bp + (size_t)k0 * ldb) : Bp, pb);
        asm volatile("cp.async.commit_group;" ::: "memory");
    }

    int lb = lane >> 3, lr = lane & 7;
    int frag_row = (lb & 1) * 8 + lr;
    int frag_col = (lb >> 1) * 8;

    int cur = 0;
    for (int k0 = 0; k0 < K; k0 += 32) {
        asm volatile("cp.async.wait_group 1;" ::: "memory");
        __syncthreads();

        // issue slab k0+64 into stage (cur+2)%3
        {
            int kn = k0 + 64;
            int nst = cur + 2; if (nst >= 3) nst -= 3;
            bool pa = a_row_ok && (kn + ac) < K;
            bool pb = b_col_ok && (kn + br) < K;
            cp16(&As[nst][ar][ac], pa ? (Ap + kn) : Ap, pa);
            cp16(&Bs[nst][br][bc], pb ? (Bp + (size_t)kn * ldb) : Bp, pb);
            asm volatile("cp.async.commit_group;" ::: "memory");
        }

        unsigned int afr[2][4];
        unsigned int bfr[2][4][2];
#pragma unroll
        for (int kk = 0; kk < 2; kk++) {
            unsigned int addr = (unsigned int)__cvta_generic_to_shared(
                &As[cur][wm * 16 + frag_row][kk * 16 + frag_col]);
            asm volatile("ldmatrix.sync.aligned.m8n8.x4.shared.b16 {%0,%1,%2,%3}, [%4];"
                : "=r"(afr[kk][0]), "=r"(afr[kk][1]), "=r"(afr[kk][2]), "=r"(afr[kk][3])
                : "r"(addr));
        }
#pragma unroll
        for (int kk = 0; kk < 2; kk++)
#pragma unroll
            for (int p = 0; p < 2; p++) {
                unsigned int addr = (unsigned int)__cvta_generic_to_shared(
                    &Bs[cur][kk * 16 + frag_row][wn * 32 + p * 16 + frag_col]);
                asm volatile("ldmatrix.sync.aligned.m8n8.x4.trans.shared.b16 {%0,%1,%2,%3}, [%4];"
                    : "=r"(bfr[kk][p * 2][0]), "=r"(bfr[kk][p * 2][1]),
                      "=r"(bfr[kk][p * 2 + 1][0]), "=r"(bfr[kk][p * 2 + 1][1])
                    : "r"(addr));
            }
#pragma unroll
        for (int kk = 0; kk < 2; kk++)
#pragma unroll
            for (int nt = 0; nt < 4; nt++) {
                asm volatile(
                    "mma.sync.aligned.m16n8k16.row.col.f32.f16.f16.f32 "
                    "{%0,%1,%2,%3}, {%4,%5,%6,%7}, {%8,%9}, {%0,%1,%2,%3};"
                    : "+f"(acc[nt][0]), "+f"(acc[nt][1]),
                      "+f"(acc[nt][2]), "+f"(acc[nt][3])
                    : "r"(afr[kk][0]), "r"(afr[kk][1]), "r"(afr[kk][2]), "r"(afr[kk][3]),
                      "r"(bfr[kk][nt][0]), "r"(bfr[kk][nt][1]));
            }

        cur = cur + 1; if (cur >= 3) cur -= 3;
    }

    int g = lane >> 2, t2 = (lane & 3) << 1;
    int row0 = bm + wm * 16 + g;
#pragma unroll
    for (int nt = 0; nt < 4; nt++) {
        int col = bn + wn * 32 + nt * 8 + t2;
        epi_store2(acc[nt][0], acc[nt][1], row0,     col, Mr, N,
                   bias, R, Rm, C, hC, ldc, scale, epi);
        epi_store2(acc[nt][2], acc[nt][3], row0 + 8, col, Mr, N,
                   bias, R, Rm, C, hC, ldc, scale, epi);
    }
}

// ---------------- layernorm: 1 warp/row, 8 rows/block, barrier-free ----------------
__global__ void __launch_bounds__(256) ln_kernel(
    const float* __restrict__ X, const float* __restrict__ gw,
    const float* __restrict__ bw, __half* __restrict__ Y)
{
    int warp = threadIdx.x >> 5;
    int lane = threadIdx.x & 31;
    int row = blockIdx.x * 8 + warp;
    const float* x = X + (size_t)row * DD;

    float4 v[3];
    float s = 0.f, q = 0.f;
#pragma unroll
    for (int k = 0; k < 3; k++) {
        v[k] = *(const float4*)(x + lane * 4 + k * 128);
        s += v[k].x + v[k].y + v[k].z + v[k].w;
        q += v[k].x * v[k].x + v[k].y * v[k].y + v[k].z * v[k].z + v[k].w * v[k].w;
    }
#pragma unroll
    for (int o = 16; o; o >>= 1) {
        s += __shfl_xor_sync(0xffffffffu, s, o);
        q += __shfl_xor_sync(0xffffffffu, q, o);
    }
    float mean = s * (1.f / DD);
    float var = q * (1.f / DD) - mean * mean;
    float inv = rsqrtf(var + 1e-6f);

    __half* y = Y + (size_t)row * DD;
#pragma unroll
    for (int k = 0; k < 3; k++) {
        int d = lane * 4 + k * 128;
        float4 g4 = *(const float4*)(gw + d);
        float4 b4 = *(const float4*)(bw + d);
        float r0 = (v[k].x - mean) * inv * g4.x + b4.x;
        float r1 = (v[k].y - mean) * inv * g4.y + b4.y;
        float r2 = (v[k].z - mean) * inv * g4.z + b4.z;
        float r3 = (v[k].w - mean) * inv * g4.w + b4.w;
        __half2 h0 = __floats2half2_rn(r0, r1);
        __half2 h1 = __floats2half2_rn(r2, r3);
        uint2 pk;
        pk.x = *(unsigned int*)&h0;
        pk.y = *(unsigned int*)&h1;
        *(uint2*)(y + d) = pk;
    }
}

// ---------------- softmax over 260 cols: fp32 scores -> half probs (stride 272) ----------------
__global__ void __launch_bounds__(128) softmax260_kernel(
    const float* __restrict__ S, __half* __restrict__ P)
{
    int row = blockIdx.x;
    const float* p = S + (size_t)row * TT;
    __half* ph = P + (size_t)row * TTP;
    int tid = threadIdx.x;
    float v0 = p[tid], v1 = p[tid + 128];
    float v2 = (tid < 4) ? p[tid + 256] : -1e30f;
    float mx = fmaxf(fmaxf(v0, v1), v2);
#pragma unroll
    for (int o = 16; o; o >>= 1) mx = fmaxf(mx, __shfl_xor_sync(0xffffffffu, mx, o));
    __shared__ float sm[4];
    if ((tid & 31) == 0) sm[tid >> 5] = mx;
    __syncthreads();
    mx = fmaxf(fmaxf(sm[0], sm[1]), fmaxf(sm[2], sm[3]));
    float e0 = __expf(v0 - mx), e1 = __expf(v1 - mx);
    float e2 = (tid < 4) ? __expf(v2 - mx) : 0.f;
    float s = e0 + e1 + e2;
#pragma unroll
    for (int o = 16; o; o >>= 1) s += __shfl_xor_sync(0xffffffffu, s, o);
    __shared__ float sq[4];
    if ((tid & 31) == 0) sq[tid >> 5] = s;
    __syncthreads();
    s = sq[0] + sq[1] + sq[2] + sq[3];
    float inv = __fdividef(1.f, s);
    ph[tid]       = __float2half_rn(e0 * inv);
    ph[tid + 128] = __float2half_rn(e1 * inv);
    if (tid < 4)  ph[tid + 256] = __float2half_rn(e2 * inv);
    if (tid >= 4 && tid < 16) ph[tid + 256] = __float2half_rn(0.f);
}

// ---------------- w = softmax(mean(tok[:, :4]) @ mk^T / sqrt(D)) ----------------
__global__ void __launch_bounds__(256) compute_w_kernel(
    const float* __restrict__ tok, const float* __restrict__ mk,
    float* __restrict__ wout)
{
    int tid = threadIdx.x;
    int p = tid >> 3;
    int b = p >> 3, m = p & 7;
    int j = tid & 7;
    const float* tb = tok + (size_t)b * TT * DD;
    const float* key = mk + (size_t)m * DD;
    float acc = 0.f;
    for (int d = j * 4; d < DD; d += 32) {
        float4 k4 = *(const float4*)(key + d);
        float4 t0 = *(const float4*)(tb + d);
        float4 t1 = *(const float4*)(tb + DD + d);
        float4 t2 = *(const float4*)(tb + 2 * DD + d);
        float4 t3 = *(const float4*)(tb + 3 * DD + d);
        acc = fmaf(0.25f * (t0.x + t1.x + t2.x + t3.x), k4.x, acc);
        acc = fmaf(0.25f * (t0.y + t1.y + t2.y + t3.y), k4.y, acc);
        acc = fmaf(0.25f * (t0.z + t1.z + t2.z + t3.z), k4.z, acc);
        acc = fmaf(0.25f * (t0.w + t1.w + t2.w + t3.w), k4.w, acc);
    }
    acc += __shfl_xor_sync(0xffffffffu, acc, 4);
    acc += __shfl_xor_sync(0xffffffffu, acc, 2);
    acc += __shfl_xor_sync(0xffffffffu, acc, 1);
    __shared__ float sl[32];
    if (j == 0) sl[p] = acc * 0.05103103630798288f;
    __syncthreads();
    if (tid < 32) {
        float logit = sl[tid];
        float mx = logit;
#pragma unroll
        for (int o = 4; o; o >>= 1) mx = fmaxf(mx, __shfl_xor_sync(0xffffffffu, mx, o));
        float e = __expf(logit - mx);
        float s = e;
#pragma unroll
        for (int o = 4; o; o >>= 1) s += __shfl_xor_sync(0xffffffffu, s, o);
        wout[tid] = e / s;
    }
}

// ---------------- hard-concrete via HW tanh ----------------
__device__ __forceinline__ float hc_z(float u, float la)
{
    u = fminf(fmaxf(u, 1e-6f), 1.0f - 1e-6f);
    float t = (__logf(u) - __logf(1.0f - u) + la) * 0.75f;
    float z = fmaf(0.6f, tanh_fast(t), 0.5f);
    return fminf(fmaxf(z, 0.0f), 1.0f);
}

// ---------------- fused delta: 1 group/thread (at HBM roof — frozen) ----------------
__global__ void __launch_bounds__(256) delta_kernel(
    const float* __restrict__ u_a, const float* __restrict__ la_a, const float* __restrict__ phi_a,
    const float* __restrict__ u_b, const float* __restrict__ la_b, const float* __restrict__ phi_b,
    const float* __restrict__ wbuf, float* __restrict__ out)
{
    __shared__ float ws[32];
    if (threadIdx.x < 32) ws[threadIdx.x] = wbuf[threadIdx.x];
    __syncthreads();

    int g = blockIdx.x * 256 + threadIdx.x;
    bool isB = g >= GCNT;
    int gg = isB ? g - GCNT : g;
    const float* up = isB ? u_b : u_a;
    const float* lp = isB ? la_b : la_a;
    const float* pp = isB ? phi_b : phi_a;

    size_t e8 = (size_t)gg * 8;
    float4 u0 = __ldcs((const float4*)(up + e8));
    float4 u1 = __ldcs((const float4*)(up + e8 + 4));
    float4 l0 = __ldcs((const float4*)(lp + e8));
    float4 l1 = __ldcs((const float4*)(lp + e8 + 4));
    float phi = __ldcs(pp + gg);

    float z[8];
    z[0] = hc_z(u0.x, l0.x); z[1] = hc_z(u0.y, l0.y);
    z[2] = hc_z(u0.z, l0.z); z[3] = hc_z(u0.w, l0.w);
    z[4] = hc_z(u1.x, l1.x); z[5] = hc_z(u1.y, l1.y);
    z[6] = hc_z(u1.z, l1.z); z[7] = hc_z(u1.w, l1.w);

    size_t base = (size_t)(isB ? GCNT : 0) + (size_t)gg;
#pragma unroll
    for (int b = 0; b < 4; b++) {
        float acc = 0.f;
#pragma unroll
        for (int m = 0; m < 8; m++) acc = fmaf(z[m], ws[b * 8 + m], acc);
        __stcs(out + (size_t)b * OUTROW + base, acc * phi);
    }
}

// ---------------- host launch ----------------
extern "C" void kernel_launch(void* const* d_in, const int* in_sizes, int n_in,
                              void* d_out, int out_size)
{
    const float* x      = (const float*)d_in[0];
    const float* u_a    = (const float*)d_in[1];
    const float* u_b    = (const float*)d_in[2];
    const float* phi_a  = (const float*)d_in[3];
    const float* phi_b  = (const float*)d_in[4];
    const float* la_a   = (const float*)d_in[5];
    const float* la_b   = (const float*)d_in[6];
    const float* Wp     = (const float*)d_in[7];
    const float* bp     = (const float*)d_in[8];
    const float* skills = (const float*)d_in[9];
    const float* cenc   = (const float*)d_in[10];
    const float* ln1_g  = (const float*)d_in[11];
    const float* ln1_b  = (const float*)d_in[12];
    const float* Wqkv   = (const float*)d_in[13];
    const float* bqkv   = (const float*)d_in[14];
    const float* Wo     = (const float*)d_in[15];
    const float* bo     = (const float*)d_in[16];
    const float* ln2_g  = (const float*)d_in[17];
    const float* ln2_b  = (const float*)d_in[18];
    const float* W1     = (const float*)d_in[19];
    const float* b1     = (const float*)d_in[20];
    const float* W2     = (const float*)d_in[21];
    const float* b2     = (const float*)d_in[22];
    const float* mk     = (const float*)d_in[23];
    float* out = (float*)d_out;

    float* scratch = nullptr;
    cudaGetSymbolAddress((void**)&scratch, g_scratch);
    __half* hbuf = nullptr;
    cudaGetSymbolAddress((void**)&hbuf, g_half);

    float* tok  = scratch + OFF_TOK;
    float* sc   = scratch + OFF_SC;
    float* ob   = scratch + OFF_O;
    float* wbuf = scratch + OFF_W;

    const __half* hx    = hbuf + HX_OFF;
    const __half* hWp   = hbuf + HWP_OFF;
    const __half* hWqkv = hbuf + HWQKV_OFF;
    const __half* hWo   = hbuf + HWO_OFF;
    const __half* hW1   = hbuf + HW1_OFF;
    const __half* hW2   = hbuf + HW2_OFF;
    const __half* hq    = hbuf + HQ_OFF;
    const __half* hkT   = hbuf + HKT_OFF;
    const __half* hv    = hbuf + HV_OFF;
    const __half* hpr   = hbuf + HPR_OFF;
    __half* hy  = hbuf + HY_OFF;
    __half* hob = hbuf + HOB_OFF;
    __half* hff = hbuf + HFF_OFF;

    // 0. convert x + weights to fp16 (vectorized), and fill skill tokens
    conv_kernel<<<(CONV_V4 + BB * 4 * DD + 255) / 256, 256>>>(
        x, Wp, Wqkv, Wo, W1, W2, skills, tok);

    // 1. h = x@Wp + bp + count_enc -> tok rows [4:260)
    hgemm_kernel<<<dim3(DD / 64, (NN + 63) / 64, BB), 256>>>(
        hx, hWp, bp, cenc, tok + 4 * DD, nullptr,
        NN, DD, DD, DD, DD, DD,
        (long long)NN * DD, 0LL, (long long)TT * DD, 0LL, 1,
        DD, 1.0f, 2);

    // 2. LN1 -> half y
    ln_kernel<<<ROWS / 8, 256>>>(tok, ln1_g, ln1_b, hy);

    // 3. qkv = y @ Wqkv + bqkv -> scattered half q / kT / v
    hgemm_kernel<<<dim3(3 * DD / 64, (ROWS + 63) / 64, 1), 256>>>(
        hy, hWqkv, bqkv, nullptr, nullptr, nullptr,
        ROWS, 3 * DD, DD, DD, 3 * DD, 3 * DD,
        0LL, 0LL, 0LL, 0LL, 1,
        0, 1.0f, 4);

    // 4. scores = q @ kT / sqrt(96)  (batched over BH=16)
    hgemm_kernel<<<dim3((TT + 63) / 64, (TT + 63) / 64, BB * HH), 256>>>(
        hq, hkT, nullptr, nullptr, sc, nullptr,
        TT, TT, DH, DH, TTP, TTP,
        (long long)TT * DH, (long long)DH * TTP, (long long)TT * TT, 0LL, 1,
        TT, 0.10206207261596577f, 0);

    // 5. softmax -> half probs (stride 272, zero tail)
    softmax260_kernel<<<BB * HH * TT, 128>>>(sc, hbuf + HPR_OFF);

    // 6. o = probs @ v -> fp32 ob (B,T,D) + half mirror
    hgemm_kernel<<<dim3((DH + 63) / 64, (TT + 63) / 64, BB * HH), 256>>>(
        hpr, hv, nullptr, nullptr, ob, hob,
        TT, DH, TTP, TTP, DH, DH,
        (long long)TT * TTP, (long long)TTP * DH,
        (long long)TT * DD, (long long)DH, HH,
        DD, 1.0f, 0);

    // 7. tok += o @ Wo + bo
    hgemm_kernel<<<dim3(DD / 64, (ROWS + 63) / 64, 1), 256>>>(
        hob, hWo, bo, tok, tok, nullptr,
        ROWS, DD, DD, DD, DD, DD,
        0LL, 0LL, 0LL, 0LL, 1,
        DD, 1.0f, 3);

    // 8. LN2 -> half y
    ln_kernel<<<ROWS / 8, 256>>>(tok, ln2_g, ln2_b, hy);

    // 9. ff = gelu(y @ W1 + b1) -> half only
    hgemm_kernel<<<dim3(2 * DD / 64, (ROWS + 63) / 64, 1), 256>>>(
        hy, hW1, b1, nullptr, nullptr, hff,
        ROWS, 2 * DD, DD, DD, 2 * DD, 2 * DD,
        0LL, 0LL, 0LL, 0LL, 1,
        2 * DD, 1.0f, 1);

    // 10. tok += ff @ W2 + b2
    hgemm_kernel<<<dim3(DD / 64, (ROWS + 63) / 64, 1), 256>>>(
        hff, hW2, b2, tok, tok, nullptr,
        ROWS, DD, 2 * DD, 2 * DD, DD, DD,
        0LL, 0LL, 0LL, 0LL, 1,
        DD, 1.0f, 3);

    // 11. w
    compute_w_kernel<<<1, 256>>>(tok, mk, wbuf);

    // 12. fused hard-concrete + contraction
    delta_kernel<<<(2 * GCNT) / 256, 256>>>(
        u_a, la_a, phi_a, u_b, la_b, phi_b, wbuf, out);
}